// round 13
// baseline (speedup 1.0000x reference)
#include <cuda_runtime.h>
#include <cuda_bf16.h>
#include <cuda_fp16.h>
#include <math_constants.h>
#include <cstdint>

// Problem constants
#define NNODES 50000
#define NEDGES 800000
#define HEADS_ 4
#define CDIM_  64
#define SLOPE_ 0.2f
#define FEAT_  256
#define MTILES 391           // ceil(50000/128)
#define ECAP   64            // cached-edge capacity (Poisson(16); fallback covers)

// ---------------------------------------------------------------------------
// Scratch
// ---------------------------------------------------------------------------
__device__ __align__(16) __half g_h1  [NNODES * FEAT_];
__device__ __align__(16) __half g_h2  [NNODES * FEAT_];
__device__ __align__(16) float  g_out1[NNODES * FEAT_];
__device__ __align__(16) __nv_bfloat16 g_Bhi1[FEAT_ * FEAT_];
__device__ __align__(16) __nv_bfloat16 g_Blo1[FEAT_ * FEAT_];
__device__ __align__(16) __nv_bfloat16 g_Bhi2[FEAT_ * FEAT_];
__device__ __align__(16) __nv_bfloat16 g_Blo2[FEAT_ * FEAT_];
__device__ __align__(16) float g_el  [NNODES * HEADS_];
__device__ __align__(16) float g_er  [NNODES * HEADS_];
__device__ int   g_rowptr[NNODES + 1];

// ---------------------------------------------------------------------------
// PTX helpers
// ---------------------------------------------------------------------------
__device__ __forceinline__ uint32_t smem_u32(const void* p) {
    uint32_t a;
    asm("{ .reg .u64 t; cvta.to.shared.u64 t, %1; cvt.u32.u64 %0, t; }" : "=r"(a) : "l"(p));
    return a;
}
__device__ __forceinline__ void ldm4(uint32_t* r, uint32_t addr) {
    asm volatile("ldmatrix.sync.aligned.m8n8.x4.shared.b16 {%0,%1,%2,%3}, [%4];"
        : "=r"(r[0]), "=r"(r[1]), "=r"(r[2]), "=r"(r[3]) : "r"(addr));
}
__device__ __forceinline__ void mma16816(float* c, const uint32_t* a, uint32_t b0, uint32_t b1) {
    asm volatile("mma.sync.aligned.m16n8k16.row.col.f32.bf16.bf16.f32 "
        "{%0,%1,%2,%3}, {%4,%5,%6,%7}, {%8,%9}, {%0,%1,%2,%3};"
        : "+f"(c[0]), "+f"(c[1]), "+f"(c[2]), "+f"(c[3])
        : "r"(a[0]), "r"(a[1]), "r"(a[2]), "r"(a[3]), "r"(b0), "r"(b1));
}
#define CP16(dst, src) asm volatile("cp.async.cg.shared.global [%0], [%1], 16;" :: "r"(dst), "l"(src))
#define CP_COMMIT()    asm volatile("cp.async.commit_group;" ::: "memory")
#define CP_WAIT(n)     asm volatile("cp.async.wait_group %0;" :: "n"(n) : "memory")

__device__ __forceinline__ uint32_t packbf2(float a, float b) {
    __nv_bfloat162 h2 = __nv_bfloat162(__float2bfloat16(a), __float2bfloat16(b));
    return *(uint32_t*)&h2;
}

// ---------------------------------------------------------------------------
// Both weight transposes + hi/lo splits in one launch
// ---------------------------------------------------------------------------
__global__ void split_bT2(const float* __restrict__ W1, const float* __restrict__ W2,
                          __nv_bfloat16* __restrict__ hi1, __nv_bfloat16* __restrict__ lo1,
                          __nv_bfloat16* __restrict__ hi2, __nv_bfloat16* __restrict__ lo2) {
    int i = blockIdx.x * blockDim.x + threadIdx.x;
    if (i >= 2 * FEAT_ * FEAT_) return;
    int which = i >= FEAT_ * FEAT_;
    int j = i - which * FEAT_ * FEAT_;
    int n = j >> 8, k = j & 255;
    const float* W = which ? W2 : W1;
    float v = W[k * 256 + n];
    __nv_bfloat16 h = __float2bfloat16(v);
    if (which) { hi2[j] = h; lo2[j] = __float2bfloat16(v - __bfloat162float(h)); }
    else       { hi1[j] = h; lo1[j] = __float2bfloat16(v - __bfloat162float(h)); }
}

// ---------------------------------------------------------------------------
// HMMA GEMM (bf16x3 split, fp32 A, fused hi/lo convert)
// BK=64: 4 k-iterations, ONE barrier each. 2-stage A + 2-stage B.
// 512 threads, 16 warps each 32(M)x32(N). CTA tile 128x128.
// Dyn smem: A_hi 2x18432 @0, A_lo @36864, B_hi 2x @73728, B_lo 2x @110592,
//           sEl @147456, sEr @148480; total 149504.
// ---------------------------------------------------------------------------
#define BKC 64
#define STR 72                          // 64 + 8 pad (144B rows, conflict-free phases)
#define TILE_BYTES (128 * STR * 2)      // 18432
#define OFF_AH 0
#define OFF_AL (2 * TILE_BYTES)         // 36864
#define OFF_BH (4 * TILE_BYTES)         // 73728
#define OFF_BL (6 * TILE_BYTES)         // 110592
#define OFF_EL (8 * TILE_BYTES)         // 147456
#define OFF_ER (OFF_EL + 1024)
#define GEMM_SMEM (OFF_ER + 1024)       // 149504

__global__ __launch_bounds__(512, 1)
void gemm_bf16x3(const float* __restrict__ A,
                 const __nv_bfloat16* __restrict__ Bhi,
                 const __nv_bfloat16* __restrict__ Blo,
                 __half* __restrict__ C,
                 const float* __restrict__ attl,
                 const float* __restrict__ attr,
                 float* __restrict__ el,
                 float* __restrict__ er,
                 int M) {
    extern __shared__ __align__(16) char smem[];
    const uint32_t sbase = smem_u32(smem);
    float* sEl = (float*)(smem + OFF_EL);
    float* sEr = (float*)(smem + OFF_ER);

    const int tid = threadIdx.x, wid = tid >> 5, lane = tid & 31;
    const int wm = wid & 3, wn = wid >> 2;
    const int row0 = blockIdx.x * 128;
    const int col0 = blockIdx.y * 128;

    const int sr = tid >> 2, sq = tid & 3;     // 4 threads per 128B row-chunk
    const int agr = row0 + sr;
    const int bgr = col0 + sr;
    const uint32_t rowOff = (uint32_t)(sr * STR * 2 + sq * 32);   // bytes in smem

    float acc[2][4][4];
#pragma unroll
    for (int mt = 0; mt < 2; mt++)
#pragma unroll
        for (int nt = 0; nt < 4; nt++)
#pragma unroll
            for (int q = 0; q < 4; q++) acc[mt][nt][q] = 0.f;

    auto stageB = [&](int kc, int buf) {
        const char* srcH = (const char*)(Bhi + (size_t)bgr * 256 + kc * BKC) + sq * 32;
        const char* srcL = (const char*)(Blo + (size_t)bgr * 256 + kc * BKC) + sq * 32;
        uint32_t dH = sbase + OFF_BH + buf * TILE_BYTES + rowOff;
        uint32_t dL = sbase + OFF_BL + buf * TILE_BYTES + rowOff;
        CP16(dH, srcH); CP16(dH + 16, srcH + 16);
        CP16(dL, srcL); CP16(dL + 16, srcL + 16);
    };
    float fv[16];
    auto loadA = [&](int kc) {
        const float4* ap = (const float4*)(A + (size_t)agr * 256 + kc * BKC) + sq * 4;
        if (agr < M) {
#pragma unroll
            for (int j = 0; j < 4; j++) *(float4*)(fv + 4 * j) = ap[j];
        } else {
#pragma unroll
            for (int j = 0; j < 16; j++) fv[j] = 0.f;
        }
    };
    auto storeA = [&](int buf) {
        uint32_t hiw[8], low[8];
#pragma unroll
        for (int p = 0; p < 8; p++) {
            float a = fv[2 * p], b = fv[2 * p + 1];
            float ha = __bfloat162float(__float2bfloat16(a));
            float hb = __bfloat162float(__float2bfloat16(b));
            hiw[p] = packbf2(a, b);
            low[p] = packbf2(a - ha, b - hb);
        }
        char* dh = smem + OFF_AH + buf * TILE_BYTES + rowOff;
        char* dl = smem + OFF_AL + buf * TILE_BYTES + rowOff;
        *(uint4*)dh = make_uint4(hiw[0], hiw[1], hiw[2], hiw[3]);
        *(uint4*)(dh + 16) = make_uint4(hiw[4], hiw[5], hiw[6], hiw[7]);
        *(uint4*)dl = make_uint4(low[0], low[1], low[2], low[3]);
        *(uint4*)(dl + 16) = make_uint4(low[4], low[5], low[6], low[7]);
    };

    const int lrow = lane & 15;
    const int lkof = (lane >> 4) * 8;

    // Prologue
    stageB(0, 0); CP_COMMIT();
    loadA(0); storeA(0);

    for (int kc = 0; kc < 4; kc++) {
        const int buf = kc & 1;
        CP_WAIT(0);          // this thread's B[kc] landed
        __syncthreads();     // all threads' B[kc] + A[kc] visible; kc-1 reads done

        if (kc < 3) {
            stageB(kc + 1, buf ^ 1); CP_COMMIT();   // targets buffer nobody reads now
            loadA(kc + 1);
        }

        const uint32_t sAh_u = sbase + OFF_AH + buf * TILE_BYTES;
        const uint32_t sAl_u = sbase + OFF_AL + buf * TILE_BYTES;
        const uint32_t sBh_u = sbase + OFF_BH + buf * TILE_BYTES;
        const uint32_t sBl_u = sbase + OFF_BL + buf * TILE_BYTES;
#pragma unroll
        for (int ks = 0; ks < 4; ks++) {
            const uint32_t kbyte = (uint32_t)((ks * 16 + lkof) * 2);
            uint32_t ah[2][4], al4[2][4];
#pragma unroll
            for (int mt = 0; mt < 2; mt++) {
                uint32_t ro = (uint32_t)((wm * 32 + mt * 16 + lrow) * STR * 2) + kbyte;
                ldm4(ah[mt], sAh_u + ro);
                ldm4(al4[mt], sAl_u + ro);
            }
            uint32_t bh[2][4], bl[2][4];
#pragma unroll
            for (int p = 0; p < 2; p++) {
                uint32_t ro = (uint32_t)((wn * 32 + p * 16 + lrow) * STR * 2) + kbyte;
                ldm4(bh[p], sBh_u + ro);
                ldm4(bl[p], sBl_u + ro);
            }
#pragma unroll
            for (int mt = 0; mt < 2; mt++)
#pragma unroll
                for (int nt = 0; nt < 4; nt++) {
                    int p = nt >> 1, o = nt & 1;
                    mma16816(acc[mt][nt], ah[mt], bh[p][o], bh[p][2 + o]);
                    mma16816(acc[mt][nt], ah[mt], bl[p][o], bl[p][2 + o]);
                    mma16816(acc[mt][nt], al4[mt], bh[p][o], bh[p][2 + o]);
                }
        }
        if (kc < 3) storeA(buf ^ 1);   // buffer read only after next barrier
    }

    // ---- Epilogue: store C (fp16) + fused attention dots ----
    __syncthreads();
    for (int i = tid; i < 256; i += 512) { sEl[i] = 0.f; sEr[i] = 0.f; }
    __syncthreads();

    const int qrow = lane >> 2, qcol = (lane & 3) * 2;
    const int head_l = wn >> 1;
    const int head = blockIdx.y * 2 + head_l;

    float wl[4][2], wr[4][2];
#pragma unroll
    for (int nt = 0; nt < 4; nt++) {
        int colIdx = (wn & 1) * 32 + nt * 8 + qcol;
        float2 l2 = *(const float2*)(attl + head * 64 + colIdx);
        float2 r2 = *(const float2*)(attr + head * 64 + colIdx);
        wl[nt][0] = l2.x; wl[nt][1] = l2.y;
        wr[nt][0] = r2.x; wr[nt][1] = r2.y;
    }

#pragma unroll
    for (int mt = 0; mt < 2; mt++) {
        int lr0 = wm * 32 + mt * 16 + qrow;
        int r0 = row0 + lr0;
        float el0 = 0.f, el1 = 0.f, er0 = 0.f, er1 = 0.f;
#pragma unroll
        for (int nt = 0; nt < 4; nt++) {
            int c = col0 + wn * 32 + nt * 8 + qcol;
            if (r0 < M)
                *(__half2*)(C + (size_t)r0 * 256 + c) =
                    __floats2half2_rn(acc[mt][nt][0], acc[mt][nt][1]);
            if (r0 + 8 < M)
                *(__half2*)(C + (size_t)(r0 + 8) * 256 + c) =
                    __floats2half2_rn(acc[mt][nt][2], acc[mt][nt][3]);
            el0 += acc[mt][nt][0] * wl[nt][0] + acc[mt][nt][1] * wl[nt][1];
            el1 += acc[mt][nt][2] * wl[nt][0] + acc[mt][nt][3] * wl[nt][1];
            er0 += acc[mt][nt][0] * wr[nt][0] + acc[mt][nt][1] * wr[nt][1];
            er1 += acc[mt][nt][2] * wr[nt][0] + acc[mt][nt][3] * wr[nt][1];
        }
#pragma unroll
        for (int off = 1; off <= 2; off <<= 1) {
            el0 += __shfl_xor_sync(0xffffffffu, el0, off);
            el1 += __shfl_xor_sync(0xffffffffu, el1, off);
            er0 += __shfl_xor_sync(0xffffffffu, er0, off);
            er1 += __shfl_xor_sync(0xffffffffu, er1, off);
        }
        if ((lane & 3) == 0) {
            atomicAdd(&sEl[lr0 * 2 + head_l], el0);
            atomicAdd(&sEl[(lr0 + 8) * 2 + head_l], el1);
            atomicAdd(&sEr[lr0 * 2 + head_l], er0);
            atomicAdd(&sEr[(lr0 + 8) * 2 + head_l], er1);
        }
    }
    __syncthreads();
    for (int i = tid; i < 256; i += 512) {
        int row = i >> 1, hl = i & 1;
        int gr = row0 + row;
        if (gr < M) {
            el[gr * 4 + blockIdx.y * 2 + hl] = sEl[i];
            er[gr * 4 + blockIdx.y * 2 + hl] = sEr[i];
        }
    }
}

// ---------------------------------------------------------------------------
// row_ptr via binary search (dst sorted ascending)
// ---------------------------------------------------------------------------
__global__ void build_rowptr(const int* __restrict__ dst) {
    int i = blockIdx.x * blockDim.x + threadIdx.x;
    if (i > NNODES) return;
    int lo = 0, hi = NEDGES;
    while (lo < hi) {
        int mid = (lo + hi) >> 1;
        if (dst[mid] < i) lo = mid + 1; else hi = mid;
    }
    g_rowptr[i] = lo;
}

// ---------------------------------------------------------------------------
// Fused edge kernel: warp-per-node, fp16 gather. Lane owns 8 fp16 features.
// ---------------------------------------------------------------------------
__device__ __forceinline__ float lrelu(float v) { return v > 0.f ? v : SLOPE_ * v; }

template <bool MEAN>
__global__ __launch_bounds__(128)
void edge_fused(const __half* __restrict__ hsrc, const int* __restrict__ src,
                const float* __restrict__ el, const float* __restrict__ er,
                const float* __restrict__ bias, float* __restrict__ out) {
    __shared__ float4 s_sc[4][ECAP];
    __shared__ int    s_src[4][ECAP];

    const int w = threadIdx.x >> 5, lane = threadIdx.x & 31;
    const int n = blockIdx.x * 4 + w;
    const int head = lane >> 3, l8 = lane & 7;
    const int col = head * 64 + l8 * 8;
    const int b = g_rowptr[n], e1 = g_rowptr[n + 1];
    const int deg = e1 - b;
    const float4 ern = ((const float4*)er)[n];
    const float ern_h = (&ern.x)[head];

    float a0x = 0.f, a0y = 0.f, a0z = 0.f, a0w = 0.f;
    float a1x = 0.f, a1y = 0.f, a1z = 0.f, a1w = 0.f;

    if (deg > 0 && deg <= ECAP) {
        for (int i = lane; i < deg; i += 32) {
            int s = src[b + i];
            s_src[w][i] = s;
            float4 e4 = ((const float4*)el)[s];
            s_sc[w][i] = make_float4(lrelu(e4.x + ern.x), lrelu(e4.y + ern.y),
                                     lrelu(e4.z + ern.z), lrelu(e4.w + ern.w));
        }
        __syncwarp();
        float m = -CUDART_INF_F;
        for (int i = l8; i < deg; i += 8) m = fmaxf(m, (&s_sc[w][i].x)[head]);
#pragma unroll
        for (int off = 4; off > 0; off >>= 1)
            m = fmaxf(m, __shfl_xor_sync(0xffffffffu, m, off));
        float ssum = 0.f;
        for (int i = l8; i < deg; i += 8) ssum += __expf((&s_sc[w][i].x)[head] - m);
#pragma unroll
        for (int off = 4; off > 0; off >>= 1)
            ssum += __shfl_xor_sync(0xffffffffu, ssum, off);
        float inv = 1.f / ssum;
        for (int i = l8; i < deg; i += 8)
            (&s_sc[w][i].x)[head] = __expf((&s_sc[w][i].x)[head] - m) * inv;
        __syncwarp();
        int i = 0;
        for (; i + 2 <= deg; i += 2) {
            float al0 = (&s_sc[w][i].x)[head];
            float al1 = (&s_sc[w][i + 1].x)[head];
            uint4 u0 = *(const uint4*)(hsrc + (size_t)s_src[w][i] * FEAT_ + col);
            uint4 u1 = *(const uint4*)(hsrc + (size_t)s_src[w][i + 1] * FEAT_ + col);
            float2 p0 = __half22float2(*(__half2*)&u0.x);
            float2 p1 = __half22float2(*(__half2*)&u0.y);
            float2 p2 = __half22float2(*(__half2*)&u0.z);
            float2 p3 = __half22float2(*(__half2*)&u0.w);
            float2 q0 = __half22float2(*(__half2*)&u1.x);
            float2 q1 = __half22float2(*(__half2*)&u1.y);
            float2 q2 = __half22float2(*(__half2*)&u1.z);
            float2 q3 = __half22float2(*(__half2*)&u1.w);
            a0x += al0 * p0.x + al1 * q0.x;  a0y += al0 * p0.y + al1 * q0.y;
            a0z += al0 * p1.x + al1 * q1.x;  a0w += al0 * p1.y + al1 * q1.y;
            a1x += al0 * p2.x + al1 * q2.x;  a1y += al0 * p2.y + al1 * q2.y;
            a1z += al0 * p3.x + al1 * q3.x;  a1w += al0 * p3.y + al1 * q3.y;
        }
        if (i < deg) {
            float al0 = (&s_sc[w][i].x)[head];
            uint4 u0 = *(const uint4*)(hsrc + (size_t)s_src[w][i] * FEAT_ + col);
            float2 p0 = __half22float2(*(__half2*)&u0.x);
            float2 p1 = __half22float2(*(__half2*)&u0.y);
            float2 p2 = __half22float2(*(__half2*)&u0.z);
            float2 p3 = __half22float2(*(__half2*)&u0.w);
            a0x += al0 * p0.x;  a0y += al0 * p0.y;
            a0z += al0 * p1.x;  a0w += al0 * p1.y;
            a1x += al0 * p2.x;  a1y += al0 * p2.y;
            a1z += al0 * p3.x;  a1w += al0 * p3.y;
        }
    } else if (deg > ECAP) {
        float m = -CUDART_INF_F;
        for (int i = l8; i < deg; i += 8) {
            int s = src[b + i];
            m = fmaxf(m, lrelu(el[s * 4 + head] + ern_h));
        }
#pragma unroll
        for (int off = 4; off > 0; off >>= 1)
            m = fmaxf(m, __shfl_xor_sync(0xffffffffu, m, off));
        float ssum = 0.f;
        for (int i = l8; i < deg; i += 8) {
            int s = src[b + i];
            ssum += __expf(lrelu(el[s * 4 + head] + ern_h) - m);
        }
#pragma unroll
        for (int off = 4; off > 0; off >>= 1)
            ssum += __shfl_xor_sync(0xffffffffu, ssum, off);
        float inv = 1.f / ssum;
        for (int i = 0; i < deg; i++) {
            int s = src[b + i];
            float a = __expf(lrelu(el[s * 4 + head] + ern_h) - m) * inv;
            uint4 u0 = *(const uint4*)(hsrc + (size_t)s * FEAT_ + col);
            float2 p0 = __half22float2(*(__half2*)&u0.x);
            float2 p1 = __half22float2(*(__half2*)&u0.y);
            float2 p2 = __half22float2(*(__half2*)&u0.z);
            float2 p3 = __half22float2(*(__half2*)&u0.w);
            a0x += a * p0.x;  a0y += a * p0.y;
            a0z += a * p1.x;  a0w += a * p1.y;
            a1x += a * p2.x;  a1y += a * p2.y;
            a1z += a * p3.x;  a1w += a * p3.y;
        }
    }

    float4 bb0 = *(const float4*)(bias + col);
    float4 bb1 = *(const float4*)(bias + col + 4);
    a0x += bb0.x; a0y += bb0.y; a0z += bb0.z; a0w += bb0.w;
    a1x += bb1.x; a1y += bb1.y; a1z += bb1.z; a1w += bb1.w;

    if (!MEAN) {
        float4* op = (float4*)(out + (size_t)n * FEAT_ + col);
        op[0] = make_float4(a0x, a0y, a0z, a0w);
        op[1] = make_float4(a1x, a1y, a1z, a1w);
    } else {
        float v[8] = {a0x, a0y, a0z, a0w, a1x, a1y, a1z, a1w};
#pragma unroll
        for (int j = 0; j < 8; j++) {
            v[j] += __shfl_xor_sync(0xffffffffu, v[j], 8);
            v[j] += __shfl_xor_sync(0xffffffffu, v[j], 16);
            v[j] *= 0.25f;
        }
        if (head == 0) {
            float4* op = (float4*)(out + (size_t)n * CDIM_ + l8 * 8);
            op[0] = make_float4(v[0], v[1], v[2], v[3]);
            op[1] = make_float4(v[4], v[5], v[6], v[7]);
        }
    }
}

// ---------------------------------------------------------------------------
// Launch
// ---------------------------------------------------------------------------
extern "C" void kernel_launch(void* const* d_in, const int* in_sizes, int n_in,
                              void* d_out, int out_size) {
    const float* x   = (const float*)d_in[0];
    const int*   src = (const int*)  d_in[1];
    const int*   dst = (const int*)  d_in[2];
    const float* W1  = (const float*)d_in[3];
    const float* al1 = (const float*)d_in[4];
    const float* ar1 = (const float*)d_in[5];
    const float* b1  = (const float*)d_in[6];
    const float* W2  = (const float*)d_in[7];
    const float* al2 = (const float*)d_in[8];
    const float* ar2 = (const float*)d_in[9];
    const float* b2  = (const float*)d_in[10];
    float* out = (float*)d_out;

    float *out1, *el, *er;
    __half *h1, *h2;
    __nv_bfloat16 *Bhi1, *Blo1, *Bhi2, *Blo2;
    cudaGetSymbolAddress((void**)&h1,   g_h1);
    cudaGetSymbolAddress((void**)&h2,   g_h2);
    cudaGetSymbolAddress((void**)&out1, g_out1);
    cudaGetSymbolAddress((void**)&el,   g_el);
    cudaGetSymbolAddress((void**)&er,   g_er);
    cudaGetSymbolAddress((void**)&Bhi1, g_Bhi1);
    cudaGetSymbolAddress((void**)&Blo1, g_Blo1);
    cudaGetSymbolAddress((void**)&Bhi2, g_Bhi2);
    cudaGetSymbolAddress((void**)&Blo2, g_Blo2);

    cudaFuncSetAttribute(gemm_bf16x3, cudaFuncAttributeMaxDynamicSharedMemorySize, GEMM_SMEM);

    dim3 gemmGrid(MTILES, 2);
    const int edgeGrid = NNODES / 4;   // 12500

    build_rowptr<<<(NNODES + 256) / 256, 256>>>(dst);
    split_bT2<<<(2 * FEAT_ * FEAT_ + 255) / 256, 256>>>(W1, W2, Bhi1, Blo1, Bhi2, Blo2);

    // ---- Layer 1 ----
    gemm_bf16x3<<<gemmGrid, 512, GEMM_SMEM>>>(x, Bhi1, Blo1, h1, al1, ar1, el, er, NNODES);
    edge_fused<false><<<edgeGrid, 128>>>(h1, src, el, er, b1, out1);

    // ---- Layer 2 ----
    gemm_bf16x3<<<gemmGrid, 512, GEMM_SMEM>>>(out1, Bhi2, Blo2, h2, al2, ar2, el, er, NNODES);
    edge_fused<true><<<edgeGrid, 128>>>(h2, src, el, er, b2, out);
}

// round 15
// speedup vs baseline: 1.0220x; 1.0220x over previous
#include <cuda_runtime.h>
#include <cuda_bf16.h>
#include <cuda_fp16.h>
#include <math_constants.h>
#include <cstdint>

// Problem constants
#define NNODES 50000
#define NEDGES 800000
#define HEADS_ 4
#define CDIM_  64
#define SLOPE_ 0.2f
#define FEAT_  256
#define MTILES 391           // ceil(50000/128)
#define ECAP   64            // cached-edge capacity (Poisson(16); fallback covers)

// ---------------------------------------------------------------------------
// Scratch
// ---------------------------------------------------------------------------
__device__ __align__(16) __half g_h1  [NNODES * FEAT_];
__device__ __align__(16) __half g_h2  [NNODES * FEAT_];
__device__ __align__(16) float  g_out1[NNODES * FEAT_];
__device__ __align__(16) __nv_bfloat16 g_Bhi1[FEAT_ * FEAT_];
__device__ __align__(16) __nv_bfloat16 g_Blo1[FEAT_ * FEAT_];
__device__ __align__(16) __nv_bfloat16 g_Bhi2[FEAT_ * FEAT_];
__device__ __align__(16) __nv_bfloat16 g_Blo2[FEAT_ * FEAT_];
__device__ __align__(16) float g_el  [NNODES * HEADS_];
__device__ __align__(16) float g_er  [NNODES * HEADS_];
__device__ int   g_rowptr[NNODES + 1];

// ---------------------------------------------------------------------------
// PTX helpers
// ---------------------------------------------------------------------------
__device__ __forceinline__ uint32_t smem_u32(const void* p) {
    uint32_t a;
    asm("{ .reg .u64 t; cvta.to.shared.u64 t, %1; cvt.u32.u64 %0, t; }" : "=r"(a) : "l"(p));
    return a;
}
__device__ __forceinline__ void ldm4(uint32_t* r, uint32_t addr) {
    asm volatile("ldmatrix.sync.aligned.m8n8.x4.shared.b16 {%0,%1,%2,%3}, [%4];"
        : "=r"(r[0]), "=r"(r[1]), "=r"(r[2]), "=r"(r[3]) : "r"(addr));
}
__device__ __forceinline__ void mma16816(float* c, const uint32_t* a, uint32_t b0, uint32_t b1) {
    asm volatile("mma.sync.aligned.m16n8k16.row.col.f32.bf16.bf16.f32 "
        "{%0,%1,%2,%3}, {%4,%5,%6,%7}, {%8,%9}, {%0,%1,%2,%3};"
        : "+f"(c[0]), "+f"(c[1]), "+f"(c[2]), "+f"(c[3])
        : "r"(a[0]), "r"(a[1]), "r"(a[2]), "r"(a[3]), "r"(b0), "r"(b1));
}
#define CP16(dst, src) asm volatile("cp.async.cg.shared.global [%0], [%1], 16;" :: "r"(dst), "l"(src))
#define CP_COMMIT()    asm volatile("cp.async.commit_group;" ::: "memory")
#define CP_WAIT(n)     asm volatile("cp.async.wait_group %0;" :: "n"(n) : "memory")

__device__ __forceinline__ uint32_t packbf2(float a, float b) {
    __nv_bfloat162 h2 = __nv_bfloat162(__float2bfloat16(a), __float2bfloat16(b));
    return *(uint32_t*)&h2;
}

// ---------------------------------------------------------------------------
// Both weight transposes + hi/lo splits in one launch
// ---------------------------------------------------------------------------
__global__ void split_bT2(const float* __restrict__ W1, const float* __restrict__ W2,
                          __nv_bfloat16* __restrict__ hi1, __nv_bfloat16* __restrict__ lo1,
                          __nv_bfloat16* __restrict__ hi2, __nv_bfloat16* __restrict__ lo2) {
    int i = blockIdx.x * blockDim.x + threadIdx.x;
    if (i >= 2 * FEAT_ * FEAT_) return;
    int which = i >= FEAT_ * FEAT_;
    int j = i - which * FEAT_ * FEAT_;
    int n = j >> 8, k = j & 255;
    const float* W = which ? W2 : W1;
    float v = W[k * 256 + n];
    __nv_bfloat16 h = __float2bfloat16(v);
    if (which) { hi2[j] = h; lo2[j] = __float2bfloat16(v - __bfloat162float(h)); }
    else       { hi1[j] = h; lo1[j] = __float2bfloat16(v - __bfloat162float(h)); }
}

// ---------------------------------------------------------------------------
// HMMA GEMM (bf16x3 split, fp32 A, fused hi/lo convert)
// CTA tile 128(M) x 64(N), BK=32, 256 threads = 8 warps each 32x32.
// grid (MTILES, 4): blockIdx.y = head. 3-stage B + 2-stage A, 1 barrier/iter.
// ~3 CTAs/SM co-resident for latency hiding.
// Dyn smem: A_hi 2x10240 @0, A_lo @20480, B_hi 3x5120 @40960,
//           B_lo 3x5120 @56320, sEl @71680 (512), sEr @72192; total 72704.
// ---------------------------------------------------------------------------
#define BKC 32
#define STR 40
#define TILEA_BYTES (128 * STR * 2)     // 10240
#define TILEB_BYTES (64 * STR * 2)      // 5120
#define OFF_AH 0
#define OFF_AL (2 * TILEA_BYTES)        // 20480
#define OFF_BH (4 * TILEA_BYTES)        // 40960
#define OFF_BL (OFF_BH + 3 * TILEB_BYTES)  // 56320
#define OFF_EL (OFF_BL + 3 * TILEB_BYTES)  // 71680
#define OFF_ER (OFF_EL + 512)
#define GEMM_SMEM (OFF_ER + 512)        // 72704

__global__ __launch_bounds__(256, 3)
void gemm_bf16x3(const float* __restrict__ A,
                 const __nv_bfloat16* __restrict__ Bhi,
                 const __nv_bfloat16* __restrict__ Blo,
                 __half* __restrict__ C,
                 const float* __restrict__ attl,
                 const float* __restrict__ attr,
                 float* __restrict__ el,
                 float* __restrict__ er,
                 int M) {
    extern __shared__ __align__(16) char smem[];
    const uint32_t sbase = smem_u32(smem);
    float* sEl = (float*)(smem + OFF_EL);
    float* sEr = (float*)(smem + OFF_ER);

    const int tid = threadIdx.x, wid = tid >> 5, lane = tid & 31;
    const int wm = wid & 3, wn = wid >> 2;        // 4 M-blocks x 2 N-blocks (32 wide)
    const int row0 = blockIdx.x * 128;
    const int head = blockIdx.y;                   // this CTA's head
    const int col0 = head * 64;

    // B staging: 64 rows, 4 threads/row x 16B (64B = 32 bf16 per row)
    const int bsr = tid >> 2, bsq = tid & 3;
    const int bgr = col0 + bsr;
    const uint32_t rowOffB = (uint32_t)(bsr * STR * 2 + bsq * 16);
    // A staging: 128 rows, 2 threads/row x 16 floats -> 32B bf16 each
    const int asr = tid >> 1, asq = tid & 1;
    const int agr = row0 + asr;
    const uint32_t rowOffA = (uint32_t)(asr * STR * 2 + asq * 32);

    float acc[2][4][4];
#pragma unroll
    for (int mt = 0; mt < 2; mt++)
#pragma unroll
        for (int nt = 0; nt < 4; nt++)
#pragma unroll
            for (int q = 0; q < 4; q++) acc[mt][nt][q] = 0.f;

    auto stageB = [&](int kc, int b3) {
        const char* srcH = (const char*)(Bhi + (size_t)bgr * 256 + kc * BKC) + bsq * 16;
        const char* srcL = (const char*)(Blo + (size_t)bgr * 256 + kc * BKC) + bsq * 16;
        CP16(sbase + OFF_BH + b3 * TILEB_BYTES + rowOffB, srcH);
        CP16(sbase + OFF_BL + b3 * TILEB_BYTES + rowOffB, srcL);
    };
    float fv[16];
    auto loadA = [&](int kc) {
        // each thread covers 16 floats: asq=0 -> floats [0,16), asq=1 -> [16,32)
        const float4* ap = (const float4*)(A + (size_t)agr * 256 + kc * BKC) + asq * 4;
        if (agr < M) {
#pragma unroll
            for (int j = 0; j < 4; j++) *(float4*)(fv + 4 * j) = ap[j];
        } else {
#pragma unroll
            for (int j = 0; j < 16; j++) fv[j] = 0.f;
        }
    };
    auto storeA = [&](int bufA) {
        uint32_t hiw[8], low[8];
#pragma unroll
        for (int p = 0; p < 8; p++) {
            float a = fv[2 * p], b = fv[2 * p + 1];
            float ha = __bfloat162float(__float2bfloat16(a));
            float hb = __bfloat162float(__float2bfloat16(b));
            hiw[p] = packbf2(a, b);
            low[p] = packbf2(a - ha, b - hb);
        }
        char* dh = smem + OFF_AH + bufA * TILEA_BYTES + rowOffA;
        char* dl = smem + OFF_AL + bufA * TILEA_BYTES + rowOffA;
        *(uint4*)dh = make_uint4(hiw[0], hiw[1], hiw[2], hiw[3]);
        *(uint4*)(dh + 16) = make_uint4(hiw[4], hiw[5], hiw[6], hiw[7]);
        *(uint4*)dl = make_uint4(low[0], low[1], low[2], low[3]);
        *(uint4*)(dl + 16) = make_uint4(low[4], low[5], low[6], low[7]);
    };

    const int lrow = lane & 15;
    const int lkof = (lane >> 4) * 8;

    // Prologue
    stageB(0, 0); CP_COMMIT();
    loadA(0); storeA(0);

    for (int kc = 0; kc < 8; kc++) {
        const int bufA = kc & 1;
        const int b3 = kc % 3;
        if (kc < 7) {
            stageB(kc + 1, (kc + 1) % 3); CP_COMMIT();
            loadA(kc + 1);
            CP_WAIT(1);
        } else {
            CP_WAIT(0);
        }
        __syncthreads();   // single barrier per iteration

        const uint32_t sAh_u = sbase + OFF_AH + bufA * TILEA_BYTES;
        const uint32_t sAl_u = sbase + OFF_AL + bufA * TILEA_BYTES;
        const uint32_t sBh_u = sbase + OFF_BH + b3 * TILEB_BYTES;
        const uint32_t sBl_u = sbase + OFF_BL + b3 * TILEB_BYTES;
#pragma unroll
        for (int ks = 0; ks < 2; ks++) {
            const uint32_t kbyte = (uint32_t)((ks * 16 + lkof) * 2);
            uint32_t ah[2][4], al4[2][4];
#pragma unroll
            for (int mt = 0; mt < 2; mt++) {
                uint32_t ro = (uint32_t)((wm * 32 + mt * 16 + lrow) * STR * 2) + kbyte;
                ldm4(ah[mt], sAh_u + ro);
                ldm4(al4[mt], sAl_u + ro);
            }
            uint32_t bh[2][4], bl[2][4];
#pragma unroll
            for (int p = 0; p < 2; p++) {
                uint32_t ro = (uint32_t)((wn * 32 + p * 16 + lrow) * STR * 2) + kbyte;
                ldm4(bh[p], sBh_u + ro);
                ldm4(bl[p], sBl_u + ro);
            }
#pragma unroll
            for (int mt = 0; mt < 2; mt++)
#pragma unroll
                for (int nt = 0; nt < 4; nt++) {
                    int p = nt >> 1, o = nt & 1;
                    mma16816(acc[mt][nt], ah[mt], bh[p][o], bh[p][2 + o]);
                    mma16816(acc[mt][nt], ah[mt], bl[p][o], bl[p][2 + o]);
                    mma16816(acc[mt][nt], al4[mt], bh[p][o], bh[p][2 + o]);
                }
        }
        if (kc < 7) storeA(bufA ^ 1);
    }

    // ---- Epilogue: store C (fp16) + fused attention dots ----
    __syncthreads();
    if (tid < 128) { sEl[tid] = 0.f; sEr[tid] = 0.f; }
    __syncthreads();

    const int qrow = lane >> 2, qcol = (lane & 3) * 2;

    float wl[4][2], wr[4][2];
#pragma unroll
    for (int nt = 0; nt < 4; nt++) {
        int colIdx = wn * 32 + nt * 8 + qcol;      // within head's 64 cols
        float2 l2 = *(const float2*)(attl + head * 64 + colIdx);
        float2 r2 = *(const float2*)(attr + head * 64 + colIdx);
        wl[nt][0] = l2.x; wl[nt][1] = l2.y;
        wr[nt][0] = r2.x; wr[nt][1] = r2.y;
    }

#pragma unroll
    for (int mt = 0; mt < 2; mt++) {
        int lr0 = wm * 32 + mt * 16 + qrow;
        int r0 = row0 + lr0;
        float el0 = 0.f, el1 = 0.f, er0 = 0.f, er1 = 0.f;
#pragma unroll
        for (int nt = 0; nt < 4; nt++) {
            int c = col0 + wn * 32 + nt * 8 + qcol;
            if (r0 < M)
                *(__half2*)(C + (size_t)r0 * 256 + c) =
                    __floats2half2_rn(acc[mt][nt][0], acc[mt][nt][1]);
            if (r0 + 8 < M)
                *(__half2*)(C + (size_t)(r0 + 8) * 256 + c) =
                    __floats2half2_rn(acc[mt][nt][2], acc[mt][nt][3]);
            el0 += acc[mt][nt][0] * wl[nt][0] + acc[mt][nt][1] * wl[nt][1];
            el1 += acc[mt][nt][2] * wl[nt][0] + acc[mt][nt][3] * wl[nt][1];
            er0 += acc[mt][nt][0] * wr[nt][0] + acc[mt][nt][1] * wr[nt][1];
            er1 += acc[mt][nt][2] * wr[nt][0] + acc[mt][nt][3] * wr[nt][1];
        }
#pragma unroll
        for (int off = 1; off <= 2; off <<= 1) {
            el0 += __shfl_xor_sync(0xffffffffu, el0, off);
            el1 += __shfl_xor_sync(0xffffffffu, el1, off);
            er0 += __shfl_xor_sync(0xffffffffu, er0, off);
            er1 += __shfl_xor_sync(0xffffffffu, er1, off);
        }
        if ((lane & 3) == 0) {
            atomicAdd(&sEl[lr0], el0);
            atomicAdd(&sEl[lr0 + 8], el1);
            atomicAdd(&sEr[lr0], er0);
            atomicAdd(&sEr[lr0 + 8], er1);
        }
    }
    __syncthreads();
    if (tid < 128) {
        int gr = row0 + tid;
        if (gr < M) {
            el[gr * 4 + head] = sEl[tid];
            er[gr * 4 + head] = sEr[tid];
        }
    }
}

// ---------------------------------------------------------------------------
// row_ptr via binary search (dst sorted ascending)
// ---------------------------------------------------------------------------
__global__ void build_rowptr(const int* __restrict__ dst) {
    int i = blockIdx.x * blockDim.x + threadIdx.x;
    if (i > NNODES) return;
    int lo = 0, hi = NEDGES;
    while (lo < hi) {
        int mid = (lo + hi) >> 1;
        if (dst[mid] < i) lo = mid + 1; else hi = mid;
    }
    g_rowptr[i] = lo;
}

// ---------------------------------------------------------------------------
// Fused edge kernel: warp-per-node, fp16 gather. Lane owns 8 fp16 features.
// ---------------------------------------------------------------------------
__device__ __forceinline__ float lrelu(float v) { return v > 0.f ? v : SLOPE_ * v; }

template <bool MEAN>
__global__ __launch_bounds__(128)
void edge_fused(const __half* __restrict__ hsrc, const int* __restrict__ src,
                const float* __restrict__ el, const float* __restrict__ er,
                const float* __restrict__ bias, float* __restrict__ out) {
    __shared__ float4 s_sc[4][ECAP];
    __shared__ int    s_src[4][ECAP];

    const int w = threadIdx.x >> 5, lane = threadIdx.x & 31;
    const int n = blockIdx.x * 4 + w;
    const int head = lane >> 3, l8 = lane & 7;
    const int col = head * 64 + l8 * 8;
    const int b = g_rowptr[n], e1 = g_rowptr[n + 1];
    const int deg = e1 - b;
    const float4 ern = ((const float4*)er)[n];
    const float ern_h = (&ern.x)[head];

    float a0x = 0.f, a0y = 0.f, a0z = 0.f, a0w = 0.f;
    float a1x = 0.f, a1y = 0.f, a1z = 0.f, a1w = 0.f;

    if (deg > 0 && deg <= ECAP) {
        for (int i = lane; i < deg; i += 32) {
            int s = src[b + i];
            s_src[w][i] = s;
            float4 e4 = ((const float4*)el)[s];
            s_sc[w][i] = make_float4(lrelu(e4.x + ern.x), lrelu(e4.y + ern.y),
                                     lrelu(e4.z + ern.z), lrelu(e4.w + ern.w));
        }
        __syncwarp();
        float m = -CUDART_INF_F;
        for (int i = l8; i < deg; i += 8) m = fmaxf(m, (&s_sc[w][i].x)[head]);
#pragma unroll
        for (int off = 4; off > 0; off >>= 1)
            m = fmaxf(m, __shfl_xor_sync(0xffffffffu, m, off));
        float ssum = 0.f;
        for (int i = l8; i < deg; i += 8) ssum += __expf((&s_sc[w][i].x)[head] - m);
#pragma unroll
        for (int off = 4; off > 0; off >>= 1)
            ssum += __shfl_xor_sync(0xffffffffu, ssum, off);
        float inv = 1.f / ssum;
        for (int i = l8; i < deg; i += 8)
            (&s_sc[w][i].x)[head] = __expf((&s_sc[w][i].x)[head] - m) * inv;
        __syncwarp();
        int i = 0;
        for (; i + 2 <= deg; i += 2) {
            float al0 = (&s_sc[w][i].x)[head];
            float al1 = (&s_sc[w][i + 1].x)[head];
            uint4 u0 = *(const uint4*)(hsrc + (size_t)s_src[w][i] * FEAT_ + col);
            uint4 u1 = *(const uint4*)(hsrc + (size_t)s_src[w][i + 1] * FEAT_ + col);
            float2 p0 = __half22float2(*(__half2*)&u0.x);
            float2 p1 = __half22float2(*(__half2*)&u0.y);
            float2 p2 = __half22float2(*(__half2*)&u0.z);
            float2 p3 = __half22float2(*(__half2*)&u0.w);
            float2 q0 = __half22float2(*(__half2*)&u1.x);
            float2 q1 = __half22float2(*(__half2*)&u1.y);
            float2 q2 = __half22float2(*(__half2*)&u1.z);
            float2 q3 = __half22float2(*(__half2*)&u1.w);
            a0x += al0 * p0.x + al1 * q0.x;  a0y += al0 * p0.y + al1 * q0.y;
            a0z += al0 * p1.x + al1 * q1.x;  a0w += al0 * p1.y + al1 * q1.y;
            a1x += al0 * p2.x + al1 * q2.x;  a1y += al0 * p2.y + al1 * q2.y;
            a1z += al0 * p3.x + al1 * q3.x;  a1w += al0 * p3.y + al1 * q3.y;
        }
        if (i < deg) {
            float al0 = (&s_sc[w][i].x)[head];
            uint4 u0 = *(const uint4*)(hsrc + (size_t)s_src[w][i] * FEAT_ + col);
            float2 p0 = __half22float2(*(__half2*)&u0.x);
            float2 p1 = __half22float2(*(__half2*)&u0.y);
            float2 p2 = __half22float2(*(__half2*)&u0.z);
            float2 p3 = __half22float2(*(__half2*)&u0.w);
            a0x += al0 * p0.x;  a0y += al0 * p0.y;
            a0z += al0 * p1.x;  a0w += al0 * p1.y;
            a1x += al0 * p2.x;  a1y += al0 * p2.y;
            a1z += al0 * p3.x;  a1w += al0 * p3.y;
        }
    } else if (deg > ECAP) {
        float m = -CUDART_INF_F;
        for (int i = l8; i < deg; i += 8) {
            int s = src[b + i];
            m = fmaxf(m, lrelu(el[s * 4 + head] + ern_h));
        }
#pragma unroll
        for (int off = 4; off > 0; off >>= 1)
            m = fmaxf(m, __shfl_xor_sync(0xffffffffu, m, off));
        float ssum = 0.f;
        for (int i = l8; i < deg; i += 8) {
            int s = src[b + i];
            ssum += __expf(lrelu(el[s * 4 + head] + ern_h) - m);
        }
#pragma unroll
        for (int off = 4; off > 0; off >>= 1)
            ssum += __shfl_xor_sync(0xffffffffu, ssum, off);
        float inv = 1.f / ssum;
        for (int i = 0; i < deg; i++) {
            int s = src[b + i];
            float a = __expf(lrelu(el[s * 4 + head] + ern_h) - m) * inv;
            uint4 u0 = *(const uint4*)(hsrc + (size_t)s * FEAT_ + col);
            float2 p0 = __half22float2(*(__half2*)&u0.x);
            float2 p1 = __half22float2(*(__half2*)&u0.y);
            float2 p2 = __half22float2(*(__half2*)&u0.z);
            float2 p3 = __half22float2(*(__half2*)&u0.w);
            a0x += a * p0.x;  a0y += a * p0.y;
            a0z += a * p1.x;  a0w += a * p1.y;
            a1x += a * p2.x;  a1y += a * p2.y;
            a1z += a * p3.x;  a1w += a * p3.y;
        }
    }

    float4 bb0 = *(const float4*)(bias + col);
    float4 bb1 = *(const float4*)(bias + col + 4);
    a0x += bb0.x; a0y += bb0.y; a0z += bb0.z; a0w += bb0.w;
    a1x += bb1.x; a1y += bb1.y; a1z += bb1.z; a1w += bb1.w;

    if (!MEAN) {
        float4* op = (float4*)(out + (size_t)n * FEAT_ + col);
        op[0] = make_float4(a0x, a0y, a0z, a0w);
        op[1] = make_float4(a1x, a1y, a1z, a1w);
    } else {
        float v[8] = {a0x, a0y, a0z, a0w, a1x, a1y, a1z, a1w};
#pragma unroll
        for (int j = 0; j < 8; j++) {
            v[j] += __shfl_xor_sync(0xffffffffu, v[j], 8);
            v[j] += __shfl_xor_sync(0xffffffffu, v[j], 16);
            v[j] *= 0.25f;
        }
        if (head == 0) {
            float4* op = (float4*)(out + (size_t)n * CDIM_ + l8 * 8);
            op[0] = make_float4(v[0], v[1], v[2], v[3]);
            op[1] = make_float4(v[4], v[5], v[6], v[7]);
        }
    }
}

// ---------------------------------------------------------------------------
// Launch
// ---------------------------------------------------------------------------
extern "C" void kernel_launch(void* const* d_in, const int* in_sizes, int n_in,
                              void* d_out, int out_size) {
    const float* x   = (const float*)d_in[0];
    const int*   src = (const int*)  d_in[1];
    const int*   dst = (const int*)  d_in[2];
    const float* W1  = (const float*)d_in[3];
    const float* al1 = (const float*)d_in[4];
    const float* ar1 = (const float*)d_in[5];
    const float* b1  = (const float*)d_in[6];
    const float* W2  = (const float*)d_in[7];
    const float* al2 = (const float*)d_in[8];
    const float* ar2 = (const float*)d_in[9];
    const float* b2  = (const float*)d_in[10];
    float* out = (float*)d_out;

    float *out1, *el, *er;
    __half *h1, *h2;
    __nv_bfloat16 *Bhi1, *Blo1, *Bhi2, *Blo2;
    cudaGetSymbolAddress((void**)&h1,   g_h1);
    cudaGetSymbolAddress((void**)&h2,   g_h2);
    cudaGetSymbolAddress((void**)&out1, g_out1);
    cudaGetSymbolAddress((void**)&el,   g_el);
    cudaGetSymbolAddress((void**)&er,   g_er);
    cudaGetSymbolAddress((void**)&Bhi1, g_Bhi1);
    cudaGetSymbolAddress((void**)&Blo1, g_Blo1);
    cudaGetSymbolAddress((void**)&Bhi2, g_Bhi2);
    cudaGetSymbolAddress((void**)&Blo2, g_Blo2);

    cudaFuncSetAttribute(gemm_bf16x3, cudaFuncAttributeMaxDynamicSharedMemorySize, GEMM_SMEM);

    dim3 gemmGrid(MTILES, 4);
    const int edgeGrid = NNODES / 4;   // 12500

    build_rowptr<<<(NNODES + 256) / 256, 256>>>(dst);
    split_bT2<<<(2 * FEAT_ * FEAT_ + 255) / 256, 256>>>(W1, W2, Bhi1, Blo1, Bhi2, Blo2);

    // ---- Layer 1 ----
    gemm_bf16x3<<<gemmGrid, 256, GEMM_SMEM>>>(x, Bhi1, Blo1, h1, al1, ar1, el, er, NNODES);
    edge_fused<false><<<edgeGrid, 128>>>(h1, src, el, er, b1, out1);

    // ---- Layer 2 ----
    gemm_bf16x3<<<gemmGrid, 256, GEMM_SMEM>>>(out1, Bhi2, Blo2, h2, al2, ar2, el, er, NNODES);
    edge_fused<true><<<edgeGrid, 128>>>(h2, src, el, er, b2, out);
}

// round 16
// speedup vs baseline: 1.2624x; 1.2352x over previous
#include <cuda_runtime.h>
#include <cuda_bf16.h>
#include <cuda_fp16.h>
#include <math_constants.h>
#include <cstdint>

// Problem constants
#define NNODES 50000
#define NEDGES 800000
#define HEADS_ 4
#define CDIM_  64
#define SLOPE_ 0.2f
#define FEAT_  256
#define MTILES 391           // ceil(50000/128)
#define ECAP   64            // cached-edge capacity (Poisson(16); fallback covers)

// ---------------------------------------------------------------------------
// Scratch
// ---------------------------------------------------------------------------
__device__ __align__(16) __half g_h1  [NNODES * FEAT_];
__device__ __align__(16) __half g_h2  [NNODES * FEAT_];
__device__ __align__(16) float  g_out1[NNODES * FEAT_];
__device__ __align__(16) __half g_Whi1[FEAT_ * FEAT_];
__device__ __align__(16) __half g_Wlo1[FEAT_ * FEAT_];
__device__ __align__(16) __half g_Whi2[FEAT_ * FEAT_];
__device__ __align__(16) __half g_Wlo2[FEAT_ * FEAT_];
__device__ __align__(16) float g_el  [NNODES * HEADS_];
__device__ __align__(16) float g_er  [NNODES * HEADS_];
__device__ int   g_rowptr[NNODES + 1];

// ---------------------------------------------------------------------------
// PTX helpers
// ---------------------------------------------------------------------------
__device__ __forceinline__ uint32_t smem_u32(const void* p) {
    uint32_t a;
    asm("{ .reg .u64 t; cvta.to.shared.u64 t, %1; cvt.u32.u64 %0, t; }" : "=r"(a) : "l"(p));
    return a;
}
__device__ __forceinline__ void ldm4(uint32_t* r, uint32_t addr) {
    asm volatile("ldmatrix.sync.aligned.m8n8.x4.shared.b16 {%0,%1,%2,%3}, [%4];"
        : "=r"(r[0]), "=r"(r[1]), "=r"(r[2]), "=r"(r[3]) : "r"(addr));
}
__device__ __forceinline__ void mma16816h(float* c, const uint32_t* a, uint32_t b0, uint32_t b1) {
    asm volatile("mma.sync.aligned.m16n8k16.row.col.f32.f16.f16.f32 "
        "{%0,%1,%2,%3}, {%4,%5,%6,%7}, {%8,%9}, {%0,%1,%2,%3};"
        : "+f"(c[0]), "+f"(c[1]), "+f"(c[2]), "+f"(c[3])
        : "r"(a[0]), "r"(a[1]), "r"(a[2]), "r"(a[3]), "r"(b0), "r"(b1));
}
#define CP16(dst, src) asm volatile("cp.async.cg.shared.global [%0], [%1], 16;" :: "r"(dst), "l"(src))
#define CP_COMMIT()    asm volatile("cp.async.commit_group;" ::: "memory")
#define CP_WAIT(n)     asm volatile("cp.async.wait_group %0;" :: "n"(n) : "memory")

__device__ __forceinline__ uint32_t packh2(float a, float b) {
    __half2 h2 = __floats2half2_rn(a, b);
    return *(uint32_t*)&h2;
}

// ---------------------------------------------------------------------------
// Both weight transposes + fp16 hi/lo splits in one launch
// ---------------------------------------------------------------------------
__global__ void split_bT2(const float* __restrict__ W1, const float* __restrict__ W2,
                          __half* __restrict__ hi1, __half* __restrict__ lo1,
                          __half* __restrict__ hi2, __half* __restrict__ lo2) {
    int i = blockIdx.x * blockDim.x + threadIdx.x;
    if (i >= 2 * FEAT_ * FEAT_) return;
    int which = i >= FEAT_ * FEAT_;
    int j = i - which * FEAT_ * FEAT_;
    int n = j >> 8, k = j & 255;
    const float* W = which ? W2 : W1;
    float v = W[k * 256 + n];
    __half h = __float2half_rn(v);
    __half l = __float2half_rn(v - __half2float(h));
    if (which) { hi2[j] = h; lo2[j] = l; }
    else       { hi1[j] = h; lo1[j] = l; }
}

// ---------------------------------------------------------------------------
// HMMA GEMM (fp16x2: A single fp16, W split fp16 hi+lo -> exact A_fp16*W)
// 3-stage B pipeline + 2-stage A, ONE barrier per k-iteration.
// 512 threads, 16 warps each 32(M)x32(N). CTA tile 128x128, BK=32.
// Dyn smem: A 2x10240 @0, B_hi 3x10240 @20480, B_lo 3x10240 @51200,
//           sEl @81920 (1024), sEr @82944; total 83968.
// ---------------------------------------------------------------------------
#define BKC 32
#define STR 40
#define TILE_BYTES (128 * STR * 2)     // 10240
#define OFF_A  0
#define OFF_BH (2 * TILE_BYTES)        // 20480
#define OFF_BL (5 * TILE_BYTES)        // 51200
#define OFF_EL (8 * TILE_BYTES)        // 81920
#define OFF_ER (OFF_EL + 1024)
#define GEMM_SMEM (OFF_ER + 1024)      // 83968

__global__ __launch_bounds__(512, 1)
void gemm_f16x2(const float* __restrict__ A,
                const __half* __restrict__ Whi,
                const __half* __restrict__ Wlo,
                __half* __restrict__ C,
                const float* __restrict__ attl,
                const float* __restrict__ attr,
                float* __restrict__ el,
                float* __restrict__ er,
                int M) {
    extern __shared__ __align__(16) char smem[];
    const uint32_t sbase = smem_u32(smem);
    float* sEl = (float*)(smem + OFF_EL);
    float* sEr = (float*)(smem + OFF_ER);

    const int tid = threadIdx.x, wid = tid >> 5, lane = tid & 31;
    const int wm = wid & 3, wn = wid >> 2;
    const int row0 = blockIdx.x * 128;
    const int col0 = blockIdx.y * 128;

    const int sr = tid >> 2, sq = tid & 3;
    const int agr = row0 + sr;
    const int bgr = col0 + sr;
    const uint32_t rowOff = (uint32_t)(sr * STR * 2 + sq * 16);

    float acc[2][4][4];
#pragma unroll
    for (int mt = 0; mt < 2; mt++)
#pragma unroll
        for (int nt = 0; nt < 4; nt++)
#pragma unroll
            for (int q = 0; q < 4; q++) acc[mt][nt][q] = 0.f;

    auto stageB = [&](int kc, int b3) {
        const char* srcH = (const char*)(Whi + (size_t)bgr * 256 + kc * BKC) + sq * 16;
        const char* srcL = (const char*)(Wlo + (size_t)bgr * 256 + kc * BKC) + sq * 16;
        CP16(sbase + OFF_BH + b3 * TILE_BYTES + rowOff, srcH);
        CP16(sbase + OFF_BL + b3 * TILE_BYTES + rowOff, srcL);
    };
    float fv[8];
    auto loadA = [&](int kc) {
        const float4* ap = (const float4*)(A + (size_t)agr * 256 + kc * BKC) + sq * 2;
        if (agr < M) {
            *(float4*)(fv)     = ap[0];
            *(float4*)(fv + 4) = ap[1];
        } else {
#pragma unroll
            for (int j = 0; j < 8; j++) fv[j] = 0.f;
        }
    };
    auto storeA = [&](int bufA) {
        uint32_t hw[4];
#pragma unroll
        for (int p = 0; p < 4; p++) hw[p] = packh2(fv[2 * p], fv[2 * p + 1]);
        *(uint4*)(smem + OFF_A + bufA * TILE_BYTES + rowOff) =
            make_uint4(hw[0], hw[1], hw[2], hw[3]);
    };

    const int lrow = lane & 15;
    const int lkof = (lane >> 4) * 8;

    // Prologue
    stageB(0, 0); CP_COMMIT();
    loadA(0); storeA(0);

    for (int kc = 0; kc < 8; kc++) {
        const int bufA = kc & 1;
        const int b3 = kc % 3;
        if (kc < 7) {
            stageB(kc + 1, (kc + 1) % 3); CP_COMMIT();
            loadA(kc + 1);
            CP_WAIT(1);
        } else {
            CP_WAIT(0);
        }
        __syncthreads();   // single barrier: B[kc] + A[bufA] visible; skew bounded

        const uint32_t sA_u  = sbase + OFF_A  + bufA * TILE_BYTES;
        const uint32_t sBh_u = sbase + OFF_BH + b3 * TILE_BYTES;
        const uint32_t sBl_u = sbase + OFF_BL + b3 * TILE_BYTES;
#pragma unroll
        for (int ks = 0; ks < 2; ks++) {
            const uint32_t kbyte = (uint32_t)((ks * 16 + lkof) * 2);
            uint32_t ah[2][4];
#pragma unroll
            for (int mt = 0; mt < 2; mt++) {
                uint32_t ro = (uint32_t)((wm * 32 + mt * 16 + lrow) * STR * 2) + kbyte;
                ldm4(ah[mt], sA_u + ro);
            }
            uint32_t bh[2][4], bl[2][4];
#pragma unroll
            for (int p = 0; p < 2; p++) {
                uint32_t ro = (uint32_t)((wn * 32 + p * 16 + lrow) * STR * 2) + kbyte;
                ldm4(bh[p], sBh_u + ro);
                ldm4(bl[p], sBl_u + ro);
            }
#pragma unroll
            for (int mt = 0; mt < 2; mt++)
#pragma unroll
                for (int nt = 0; nt < 4; nt++) {
                    int p = nt >> 1, o = nt & 1;
                    mma16816h(acc[mt][nt], ah[mt], bh[p][o], bh[p][2 + o]);
                    mma16816h(acc[mt][nt], ah[mt], bl[p][o], bl[p][2 + o]);
                }
        }
        if (kc < 7) storeA(bufA ^ 1);   // buffer read only after next barrier
    }

    // ---- Epilogue: store C (fp16) + fused attention dots ----
    __syncthreads();
    for (int i = tid; i < 256; i += 512) { sEl[i] = 0.f; sEr[i] = 0.f; }
    __syncthreads();

    const int qrow = lane >> 2, qcol = (lane & 3) * 2;
    const int head_l = wn >> 1;
    const int head = blockIdx.y * 2 + head_l;

    float wl[4][2], wr[4][2];
#pragma unroll
    for (int nt = 0; nt < 4; nt++) {
        int colIdx = (wn & 1) * 32 + nt * 8 + qcol;
        float2 l2 = *(const float2*)(attl + head * 64 + colIdx);
        float2 r2 = *(const float2*)(attr + head * 64 + colIdx);
        wl[nt][0] = l2.x; wl[nt][1] = l2.y;
        wr[nt][0] = r2.x; wr[nt][1] = r2.y;
    }

#pragma unroll
    for (int mt = 0; mt < 2; mt++) {
        int lr0 = wm * 32 + mt * 16 + qrow;
        int r0 = row0 + lr0;
        float el0 = 0.f, el1 = 0.f, er0 = 0.f, er1 = 0.f;
#pragma unroll
        for (int nt = 0; nt < 4; nt++) {
            int c = col0 + wn * 32 + nt * 8 + qcol;
            if (r0 < M)
                *(__half2*)(C + (size_t)r0 * 256 + c) =
                    __floats2half2_rn(acc[mt][nt][0], acc[mt][nt][1]);
            if (r0 + 8 < M)
                *(__half2*)(C + (size_t)(r0 + 8) * 256 + c) =
                    __floats2half2_rn(acc[mt][nt][2], acc[mt][nt][3]);
            el0 += acc[mt][nt][0] * wl[nt][0] + acc[mt][nt][1] * wl[nt][1];
            el1 += acc[mt][nt][2] * wl[nt][0] + acc[mt][nt][3] * wl[nt][1];
            er0 += acc[mt][nt][0] * wr[nt][0] + acc[mt][nt][1] * wr[nt][1];
            er1 += acc[mt][nt][2] * wr[nt][0] + acc[mt][nt][3] * wr[nt][1];
        }
#pragma unroll
        for (int off = 1; off <= 2; off <<= 1) {
            el0 += __shfl_xor_sync(0xffffffffu, el0, off);
            el1 += __shfl_xor_sync(0xffffffffu, el1, off);
            er0 += __shfl_xor_sync(0xffffffffu, er0, off);
            er1 += __shfl_xor_sync(0xffffffffu, er1, off);
        }
        if ((lane & 3) == 0) {
            atomicAdd(&sEl[lr0 * 2 + head_l], el0);
            atomicAdd(&sEl[(lr0 + 8) * 2 + head_l], el1);
            atomicAdd(&sEr[lr0 * 2 + head_l], er0);
            atomicAdd(&sEr[(lr0 + 8) * 2 + head_l], er1);
        }
    }
    __syncthreads();
    for (int i = tid; i < 256; i += 512) {
        int row = i >> 1, hl = i & 1;
        int gr = row0 + row;
        if (gr < M) {
            el[gr * 4 + blockIdx.y * 2 + hl] = sEl[i];
            er[gr * 4 + blockIdx.y * 2 + hl] = sEr[i];
        }
    }
}

// ---------------------------------------------------------------------------
// row_ptr via binary search (dst sorted ascending)
// ---------------------------------------------------------------------------
__global__ void build_rowptr(const int* __restrict__ dst) {
    int i = blockIdx.x * blockDim.x + threadIdx.x;
    if (i > NNODES) return;
    int lo = 0, hi = NEDGES;
    while (lo < hi) {
        int mid = (lo + hi) >> 1;
        if (dst[mid] < i) lo = mid + 1; else hi = mid;
    }
    g_rowptr[i] = lo;
}

// ---------------------------------------------------------------------------
// Fused edge kernel: warp-per-node, fp16 gather. Lane owns 8 fp16 features.
// ---------------------------------------------------------------------------
__device__ __forceinline__ float lrelu(float v) { return v > 0.f ? v : SLOPE_ * v; }

template <bool MEAN>
__global__ __launch_bounds__(128)
void edge_fused(const __half* __restrict__ hsrc, const int* __restrict__ src,
                const float* __restrict__ el, const float* __restrict__ er,
                const float* __restrict__ bias, float* __restrict__ out) {
    __shared__ float4 s_sc[4][ECAP];
    __shared__ int    s_src[4][ECAP];

    const int w = threadIdx.x >> 5, lane = threadIdx.x & 31;
    const int n = blockIdx.x * 4 + w;
    const int head = lane >> 3, l8 = lane & 7;
    const int col = head * 64 + l8 * 8;
    const int b = g_rowptr[n], e1 = g_rowptr[n + 1];
    const int deg = e1 - b;
    const float4 ern = ((const float4*)er)[n];
    const float ern_h = (&ern.x)[head];

    float a0x = 0.f, a0y = 0.f, a0z = 0.f, a0w = 0.f;
    float a1x = 0.f, a1y = 0.f, a1z = 0.f, a1w = 0.f;

    if (deg > 0 && deg <= ECAP) {
        for (int i = lane; i < deg; i += 32) {
            int s = src[b + i];
            s_src[w][i] = s;
            float4 e4 = ((const float4*)el)[s];
            s_sc[w][i] = make_float4(lrelu(e4.x + ern.x), lrelu(e4.y + ern.y),
                                     lrelu(e4.z + ern.z), lrelu(e4.w + ern.w));
        }
        __syncwarp();
        float m = -CUDART_INF_F;
        for (int i = l8; i < deg; i += 8) m = fmaxf(m, (&s_sc[w][i].x)[head]);
#pragma unroll
        for (int off = 4; off > 0; off >>= 1)
            m = fmaxf(m, __shfl_xor_sync(0xffffffffu, m, off));
        float ssum = 0.f;
        for (int i = l8; i < deg; i += 8) ssum += __expf((&s_sc[w][i].x)[head] - m);
#pragma unroll
        for (int off = 4; off > 0; off >>= 1)
            ssum += __shfl_xor_sync(0xffffffffu, ssum, off);
        float inv = 1.f / ssum;
        for (int i = l8; i < deg; i += 8)
            (&s_sc[w][i].x)[head] = __expf((&s_sc[w][i].x)[head] - m) * inv;
        __syncwarp();
        int i = 0;
        for (; i + 2 <= deg; i += 2) {
            float al0 = (&s_sc[w][i].x)[head];
            float al1 = (&s_sc[w][i + 1].x)[head];
            uint4 u0 = *(const uint4*)(hsrc + (size_t)s_src[w][i] * FEAT_ + col);
            uint4 u1 = *(const uint4*)(hsrc + (size_t)s_src[w][i + 1] * FEAT_ + col);
            float2 p0 = __half22float2(*(__half2*)&u0.x);
            float2 p1 = __half22float2(*(__half2*)&u0.y);
            float2 p2 = __half22float2(*(__half2*)&u0.z);
            float2 p3 = __half22float2(*(__half2*)&u0.w);
            float2 q0 = __half22float2(*(__half2*)&u1.x);
            float2 q1 = __half22float2(*(__half2*)&u1.y);
            float2 q2 = __half22float2(*(__half2*)&u1.z);
            float2 q3 = __half22float2(*(__half2*)&u1.w);
            a0x += al0 * p0.x + al1 * q0.x;  a0y += al0 * p0.y + al1 * q0.y;
            a0z += al0 * p1.x + al1 * q1.x;  a0w += al0 * p1.y + al1 * q1.y;
            a1x += al0 * p2.x + al1 * q2.x;  a1y += al0 * p2.y + al1 * q2.y;
            a1z += al0 * p3.x + al1 * q3.x;  a1w += al0 * p3.y + al1 * q3.y;
        }
        if (i < deg) {
            float al0 = (&s_sc[w][i].x)[head];
            uint4 u0 = *(const uint4*)(hsrc + (size_t)s_src[w][i] * FEAT_ + col);
            float2 p0 = __half22float2(*(__half2*)&u0.x);
            float2 p1 = __half22float2(*(__half2*)&u0.y);
            float2 p2 = __half22float2(*(__half2*)&u0.z);
            float2 p3 = __half22float2(*(__half2*)&u0.w);
            a0x += al0 * p0.x;  a0y += al0 * p0.y;
            a0z += al0 * p1.x;  a0w += al0 * p1.y;
            a1x += al0 * p2.x;  a1y += al0 * p2.y;
            a1z += al0 * p3.x;  a1w += al0 * p3.y;
        }
    } else if (deg > ECAP) {
        float m = -CUDART_INF_F;
        for (int i = l8; i < deg; i += 8) {
            int s = src[b + i];
            m = fmaxf(m, lrelu(el[s * 4 + head] + ern_h));
        }
#pragma unroll
        for (int off = 4; off > 0; off >>= 1)
            m = fmaxf(m, __shfl_xor_sync(0xffffffffu, m, off));
        float ssum = 0.f;
        for (int i = l8; i < deg; i += 8) {
            int s = src[b + i];
            ssum += __expf(lrelu(el[s * 4 + head] + ern_h) - m);
        }
#pragma unroll
        for (int off = 4; off > 0; off >>= 1)
            ssum += __shfl_xor_sync(0xffffffffu, ssum, off);
        float inv = 1.f / ssum;
        for (int i = 0; i < deg; i++) {
            int s = src[b + i];
            float a = __expf(lrelu(el[s * 4 + head] + ern_h) - m) * inv;
            uint4 u0 = *(const uint4*)(hsrc + (size_t)s * FEAT_ + col);
            float2 p0 = __half22float2(*(__half2*)&u0.x);
            float2 p1 = __half22float2(*(__half2*)&u0.y);
            float2 p2 = __half22float2(*(__half2*)&u0.z);
            float2 p3 = __half22float2(*(__half2*)&u0.w);
            a0x += a * p0.x;  a0y += a * p0.y;
            a0z += a * p1.x;  a0w += a * p1.y;
            a1x += a * p2.x;  a1y += a * p2.y;
            a1z += a * p3.x;  a1w += a * p3.y;
        }
    }

    float4 bb0 = *(const float4*)(bias + col);
    float4 bb1 = *(const float4*)(bias + col + 4);
    a0x += bb0.x; a0y += bb0.y; a0z += bb0.z; a0w += bb0.w;
    a1x += bb1.x; a1y += bb1.y; a1z += bb1.z; a1w += bb1.w;

    if (!MEAN) {
        float4* op = (float4*)(out + (size_t)n * FEAT_ + col);
        op[0] = make_float4(a0x, a0y, a0z, a0w);
        op[1] = make_float4(a1x, a1y, a1z, a1w);
    } else {
        float v[8] = {a0x, a0y, a0z, a0w, a1x, a1y, a1z, a1w};
#pragma unroll
        for (int j = 0; j < 8; j++) {
            v[j] += __shfl_xor_sync(0xffffffffu, v[j], 8);
            v[j] += __shfl_xor_sync(0xffffffffu, v[j], 16);
            v[j] *= 0.25f;
        }
        if (head == 0) {
            float4* op = (float4*)(out + (size_t)n * CDIM_ + l8 * 8);
            op[0] = make_float4(v[0], v[1], v[2], v[3]);
            op[1] = make_float4(v[4], v[5], v[6], v[7]);
        }
    }
}

// ---------------------------------------------------------------------------
// Launch
// ---------------------------------------------------------------------------
extern "C" void kernel_launch(void* const* d_in, const int* in_sizes, int n_in,
                              void* d_out, int out_size) {
    const float* x   = (const float*)d_in[0];
    const int*   src = (const int*)  d_in[1];
    const int*   dst = (const int*)  d_in[2];
    const float* W1  = (const float*)d_in[3];
    const float* al1 = (const float*)d_in[4];
    const float* ar1 = (const float*)d_in[5];
    const float* b1  = (const float*)d_in[6];
    const float* W2  = (const float*)d_in[7];
    const float* al2 = (const float*)d_in[8];
    const float* ar2 = (const float*)d_in[9];
    const float* b2  = (const float*)d_in[10];
    float* out = (float*)d_out;

    float *out1, *el, *er;
    __half *h1, *h2, *Whi1, *Wlo1, *Whi2, *Wlo2;
    cudaGetSymbolAddress((void**)&h1,   g_h1);
    cudaGetSymbolAddress((void**)&h2,   g_h2);
    cudaGetSymbolAddress((void**)&out1, g_out1);
    cudaGetSymbolAddress((void**)&el,   g_el);
    cudaGetSymbolAddress((void**)&er,   g_er);
    cudaGetSymbolAddress((void**)&Whi1, g_Whi1);
    cudaGetSymbolAddress((void**)&Wlo1, g_Wlo1);
    cudaGetSymbolAddress((void**)&Whi2, g_Whi2);
    cudaGetSymbolAddress((void**)&Wlo2, g_Wlo2);

    cudaFuncSetAttribute(gemm_f16x2, cudaFuncAttributeMaxDynamicSharedMemorySize, GEMM_SMEM);

    dim3 gemmGrid(MTILES, 2);
    const int edgeGrid = NNODES / 4;   // 12500

    build_rowptr<<<(NNODES + 256) / 256, 256>>>(dst);
    split_bT2<<<(2 * FEAT_ * FEAT_ + 255) / 256, 256>>>(W1, W2, Whi1, Wlo1, Whi2, Wlo2);

    // ---- Layer 1 ----
    gemm_f16x2<<<gemmGrid, 512, GEMM_SMEM>>>(x, Whi1, Wlo1, h1, al1, ar1, el, er, NNODES);
    edge_fused<false><<<edgeGrid, 128>>>(h1, src, el, er, b1, out1);

    // ---- Layer 2 ----
    gemm_f16x2<<<gemmGrid, 512, GEMM_SMEM>>>(out1, Whi2, Wlo2, h2, al2, ar2, el, er, NNODES);
    edge_fused<true><<<edgeGrid, 128>>>(h2, src, el, er, b2, out);
}

// round 17
// speedup vs baseline: 1.3905x; 1.1015x over previous
#include <cuda_runtime.h>
#include <cuda_bf16.h>
#include <cuda_fp16.h>
#include <math_constants.h>
#include <cstdint>

// Problem constants
#define NNODES 50000
#define NEDGES 800000
#define HEADS_ 4
#define CDIM_  64
#define SLOPE_ 0.2f
#define FEAT_  256
#define MTILES 391           // ceil(50000/128)
#define ECAP   64            // cached-edge capacity (Poisson(16); fallback covers)

// ---------------------------------------------------------------------------
// Scratch
// ---------------------------------------------------------------------------
__device__ __align__(16) __half g_h1  [NNODES * FEAT_];
__device__ __align__(16) __half g_h2  [NNODES * FEAT_];
__device__ __align__(16) float  g_out1[NNODES * FEAT_];
__device__ __align__(16) __half g_W1h [FEAT_ * FEAT_];
__device__ __align__(16) __half g_W2h [FEAT_ * FEAT_];
__device__ __align__(16) float g_el  [NNODES * HEADS_];
__device__ __align__(16) float g_er  [NNODES * HEADS_];
__device__ int   g_rowptr[NNODES + 1];

// ---------------------------------------------------------------------------
// PTX helpers
// ---------------------------------------------------------------------------
__device__ __forceinline__ uint32_t smem_u32(const void* p) {
    uint32_t a;
    asm("{ .reg .u64 t; cvta.to.shared.u64 t, %1; cvt.u32.u64 %0, t; }" : "=r"(a) : "l"(p));
    return a;
}
__device__ __forceinline__ void ldm4(uint32_t* r, uint32_t addr) {
    asm volatile("ldmatrix.sync.aligned.m8n8.x4.shared.b16 {%0,%1,%2,%3}, [%4];"
        : "=r"(r[0]), "=r"(r[1]), "=r"(r[2]), "=r"(r[3]) : "r"(addr));
}
__device__ __forceinline__ void mma16816h(float* c, const uint32_t* a, uint32_t b0, uint32_t b1) {
    asm volatile("mma.sync.aligned.m16n8k16.row.col.f32.f16.f16.f32 "
        "{%0,%1,%2,%3}, {%4,%5,%6,%7}, {%8,%9}, {%0,%1,%2,%3};"
        : "+f"(c[0]), "+f"(c[1]), "+f"(c[2]), "+f"(c[3])
        : "r"(a[0]), "r"(a[1]), "r"(a[2]), "r"(a[3]), "r"(b0), "r"(b1));
}
#define CP16(dst, src) asm volatile("cp.async.cg.shared.global [%0], [%1], 16;" :: "r"(dst), "l"(src))
#define CP_COMMIT()    asm volatile("cp.async.commit_group;" ::: "memory")
#define CP_WAIT(n)     asm volatile("cp.async.wait_group %0;" :: "n"(n) : "memory")

__device__ __forceinline__ uint32_t packh2(float a, float b) {
    __half2 h2 = __floats2half2_rn(a, b);
    return *(uint32_t*)&h2;
}

// ---------------------------------------------------------------------------
// Both weight transposes -> fp16, one launch
// ---------------------------------------------------------------------------
__global__ void split_bT2(const float* __restrict__ W1, const float* __restrict__ W2,
                          __half* __restrict__ w1h, __half* __restrict__ w2h) {
    int i = blockIdx.x * blockDim.x + threadIdx.x;
    if (i >= 2 * FEAT_ * FEAT_) return;
    int which = i >= FEAT_ * FEAT_;
    int j = i - which * FEAT_ * FEAT_;
    int n = j >> 8, k = j & 255;
    const float* W = which ? W2 : W1;
    __half h = __float2half_rn(W[k * 256 + n]);
    if (which) w2h[j] = h; else w1h[j] = h;
}

// ---------------------------------------------------------------------------
// HMMA GEMM (pure fp16, single pass). fp32 A converted in-kernel.
// 3-stage B ring + 2-stage A, ONE barrier per k-iteration.
// 512 threads, 16 warps each 32(M)x32(N). CTA tile 128x128, BK=32.
// Dyn smem: A 2x10240 @0, B 3x10240 @20480, sEl @51200 (1024), sEr @52224;
//           total 53248.
// ---------------------------------------------------------------------------
#define BKC 32
#define STR 40
#define TILE_BYTES (128 * STR * 2)     // 10240
#define OFF_A  0
#define OFF_B  (2 * TILE_BYTES)        // 20480
#define OFF_EL (5 * TILE_BYTES)        // 51200
#define OFF_ER (OFF_EL + 1024)
#define GEMM_SMEM (OFF_ER + 1024)      // 53248

__global__ __launch_bounds__(512, 1)
void gemm_f16(const float* __restrict__ A,
              const __half* __restrict__ Wh,
              __half* __restrict__ C,
              const float* __restrict__ attl,
              const float* __restrict__ attr,
              float* __restrict__ el,
              float* __restrict__ er,
              int M) {
    extern __shared__ __align__(16) char smem[];
    const uint32_t sbase = smem_u32(smem);
    float* sEl = (float*)(smem + OFF_EL);
    float* sEr = (float*)(smem + OFF_ER);

    const int tid = threadIdx.x, wid = tid >> 5, lane = tid & 31;
    const int wm = wid & 3, wn = wid >> 2;
    const int row0 = blockIdx.x * 128;
    const int col0 = blockIdx.y * 128;

    const int sr = tid >> 2, sq = tid & 3;
    const int agr = row0 + sr;
    const int bgr = col0 + sr;
    const uint32_t rowOff = (uint32_t)(sr * STR * 2 + sq * 16);

    float acc[2][4][4];
#pragma unroll
    for (int mt = 0; mt < 2; mt++)
#pragma unroll
        for (int nt = 0; nt < 4; nt++)
#pragma unroll
            for (int q = 0; q < 4; q++) acc[mt][nt][q] = 0.f;

    auto stageB = [&](int kc, int b3) {
        const char* srcH = (const char*)(Wh + (size_t)bgr * 256 + kc * BKC) + sq * 16;
        CP16(sbase + OFF_B + b3 * TILE_BYTES + rowOff, srcH);
    };
    float fv[8];
    auto loadA = [&](int kc) {
        const float4* ap = (const float4*)(A + (size_t)agr * 256 + kc * BKC) + sq * 2;
        if (agr < M) {
            *(float4*)(fv)     = ap[0];
            *(float4*)(fv + 4) = ap[1];
        } else {
#pragma unroll
            for (int j = 0; j < 8; j++) fv[j] = 0.f;
        }
    };
    auto storeA = [&](int bufA) {
        uint32_t hw[4];
#pragma unroll
        for (int p = 0; p < 4; p++) hw[p] = packh2(fv[2 * p], fv[2 * p + 1]);
        *(uint4*)(smem + OFF_A + bufA * TILE_BYTES + rowOff) =
            make_uint4(hw[0], hw[1], hw[2], hw[3]);
    };

    const int lrow = lane & 15;
    const int lkof = (lane >> 4) * 8;

    // Prologue
    stageB(0, 0); CP_COMMIT();
    loadA(0); storeA(0);

    for (int kc = 0; kc < 8; kc++) {
        const int bufA = kc & 1;
        const int b3 = kc % 3;
        if (kc < 7) {
            stageB(kc + 1, (kc + 1) % 3); CP_COMMIT();
            loadA(kc + 1);
            CP_WAIT(1);
        } else {
            CP_WAIT(0);
        }
        __syncthreads();   // single barrier: B[kc] + A[bufA] visible; skew bounded

        const uint32_t sA_u = sbase + OFF_A + bufA * TILE_BYTES;
        const uint32_t sB_u = sbase + OFF_B + b3 * TILE_BYTES;
#pragma unroll
        for (int ks = 0; ks < 2; ks++) {
            const uint32_t kbyte = (uint32_t)((ks * 16 + lkof) * 2);
            uint32_t ah[2][4];
#pragma unroll
            for (int mt = 0; mt < 2; mt++) {
                uint32_t ro = (uint32_t)((wm * 32 + mt * 16 + lrow) * STR * 2) + kbyte;
                ldm4(ah[mt], sA_u + ro);
            }
            uint32_t bh[2][4];
#pragma unroll
            for (int p = 0; p < 2; p++) {
                uint32_t ro = (uint32_t)((wn * 32 + p * 16 + lrow) * STR * 2) + kbyte;
                ldm4(bh[p], sB_u + ro);
            }
#pragma unroll
            for (int mt = 0; mt < 2; mt++)
#pragma unroll
                for (int nt = 0; nt < 4; nt++) {
                    int p = nt >> 1, o = nt & 1;
                    mma16816h(acc[mt][nt], ah[mt], bh[p][o], bh[p][2 + o]);
                }
        }
        if (kc < 7) storeA(bufA ^ 1);
    }

    // ---- Epilogue: store C (fp16) + fused attention dots ----
    __syncthreads();
    for (int i = tid; i < 256; i += 512) { sEl[i] = 0.f; sEr[i] = 0.f; }
    __syncthreads();

    const int qrow = lane >> 2, qcol = (lane & 3) * 2;
    const int head_l = wn >> 1;
    const int head = blockIdx.y * 2 + head_l;

    float wl[4][2], wr[4][2];
#pragma unroll
    for (int nt = 0; nt < 4; nt++) {
        int colIdx = (wn & 1) * 32 + nt * 8 + qcol;
        float2 l2 = *(const float2*)(attl + head * 64 + colIdx);
        float2 r2 = *(const float2*)(attr + head * 64 + colIdx);
        wl[nt][0] = l2.x; wl[nt][1] = l2.y;
        wr[nt][0] = r2.x; wr[nt][1] = r2.y;
    }

#pragma unroll
    for (int mt = 0; mt < 2; mt++) {
        int lr0 = wm * 32 + mt * 16 + qrow;
        int r0 = row0 + lr0;
        float el0 = 0.f, el1 = 0.f, er0 = 0.f, er1 = 0.f;
#pragma unroll
        for (int nt = 0; nt < 4; nt++) {
            int c = col0 + wn * 32 + nt * 8 + qcol;
            if (r0 < M)
                *(__half2*)(C + (size_t)r0 * 256 + c) =
                    __floats2half2_rn(acc[mt][nt][0], acc[mt][nt][1]);
            if (r0 + 8 < M)
                *(__half2*)(C + (size_t)(r0 + 8) * 256 + c) =
                    __floats2half2_rn(acc[mt][nt][2], acc[mt][nt][3]);
            el0 += acc[mt][nt][0] * wl[nt][0] + acc[mt][nt][1] * wl[nt][1];
            el1 += acc[mt][nt][2] * wl[nt][0] + acc[mt][nt][3] * wl[nt][1];
            er0 += acc[mt][nt][0] * wr[nt][0] + acc[mt][nt][1] * wr[nt][1];
            er1 += acc[mt][nt][2] * wr[nt][0] + acc[mt][nt][3] * wr[nt][1];
        }
#pragma unroll
        for (int off = 1; off <= 2; off <<= 1) {
            el0 += __shfl_xor_sync(0xffffffffu, el0, off);
            el1 += __shfl_xor_sync(0xffffffffu, el1, off);
            er0 += __shfl_xor_sync(0xffffffffu, er0, off);
            er1 += __shfl_xor_sync(0xffffffffu, er1, off);
        }
        if ((lane & 3) == 0) {
            atomicAdd(&sEl[lr0 * 2 + head_l], el0);
            atomicAdd(&sEl[(lr0 + 8) * 2 + head_l], el1);
            atomicAdd(&sEr[lr0 * 2 + head_l], er0);
            atomicAdd(&sEr[(lr0 + 8) * 2 + head_l], er1);
        }
    }
    __syncthreads();
    for (int i = tid; i < 256; i += 512) {
        int row = i >> 1, hl = i & 1;
        int gr = row0 + row;
        if (gr < M) {
            el[gr * 4 + blockIdx.y * 2 + hl] = sEl[i];
            er[gr * 4 + blockIdx.y * 2 + hl] = sEr[i];
        }
    }
}

// ---------------------------------------------------------------------------
// row_ptr via binary search (dst sorted ascending)
// ---------------------------------------------------------------------------
__global__ void build_rowptr(const int* __restrict__ dst) {
    int i = blockIdx.x * blockDim.x + threadIdx.x;
    if (i > NNODES) return;
    int lo = 0, hi = NEDGES;
    while (lo < hi) {
        int mid = (lo + hi) >> 1;
        if (dst[mid] < i) lo = mid + 1; else hi = mid;
    }
    g_rowptr[i] = lo;
}

// ---------------------------------------------------------------------------
// Fused edge kernel: warp-per-node, fp16 gather. Lane owns 8 fp16 features.
// ---------------------------------------------------------------------------
__device__ __forceinline__ float lrelu(float v) { return v > 0.f ? v : SLOPE_ * v; }

template <bool MEAN>
__global__ __launch_bounds__(128)
void edge_fused(const __half* __restrict__ hsrc, const int* __restrict__ src,
                const float* __restrict__ el, const float* __restrict__ er,
                const float* __restrict__ bias, float* __restrict__ out) {
    __shared__ float4 s_sc[4][ECAP];
    __shared__ int    s_src[4][ECAP];

    const int w = threadIdx.x >> 5, lane = threadIdx.x & 31;
    const int n = blockIdx.x * 4 + w;
    const int head = lane >> 3, l8 = lane & 7;
    const int col = head * 64 + l8 * 8;
    const int b = g_rowptr[n], e1 = g_rowptr[n + 1];
    const int deg = e1 - b;
    const float4 ern = ((const float4*)er)[n];
    const float ern_h = (&ern.x)[head];

    float a0x = 0.f, a0y = 0.f, a0z = 0.f, a0w = 0.f;
    float a1x = 0.f, a1y = 0.f, a1z = 0.f, a1w = 0.f;

    if (deg > 0 && deg <= ECAP) {
        for (int i = lane; i < deg; i += 32) {
            int s = src[b + i];
            s_src[w][i] = s;
            float4 e4 = ((const float4*)el)[s];
            s_sc[w][i] = make_float4(lrelu(e4.x + ern.x), lrelu(e4.y + ern.y),
                                     lrelu(e4.z + ern.z), lrelu(e4.w + ern.w));
        }
        __syncwarp();
        float m = -CUDART_INF_F;
        for (int i = l8; i < deg; i += 8) m = fmaxf(m, (&s_sc[w][i].x)[head]);
#pragma unroll
        for (int off = 4; off > 0; off >>= 1)
            m = fmaxf(m, __shfl_xor_sync(0xffffffffu, m, off));
        float ssum = 0.f;
        for (int i = l8; i < deg; i += 8) ssum += __expf((&s_sc[w][i].x)[head] - m);
#pragma unroll
        for (int off = 4; off > 0; off >>= 1)
            ssum += __shfl_xor_sync(0xffffffffu, ssum, off);
        float inv = 1.f / ssum;
        for (int i = l8; i < deg; i += 8)
            (&s_sc[w][i].x)[head] = __expf((&s_sc[w][i].x)[head] - m) * inv;
        __syncwarp();
        int i = 0;
        for (; i + 2 <= deg; i += 2) {
            float al0 = (&s_sc[w][i].x)[head];
            float al1 = (&s_sc[w][i + 1].x)[head];
            uint4 u0 = *(const uint4*)(hsrc + (size_t)s_src[w][i] * FEAT_ + col);
            uint4 u1 = *(const uint4*)(hsrc + (size_t)s_src[w][i + 1] * FEAT_ + col);
            float2 p0 = __half22float2(*(__half2*)&u0.x);
            float2 p1 = __half22float2(*(__half2*)&u0.y);
            float2 p2 = __half22float2(*(__half2*)&u0.z);
            float2 p3 = __half22float2(*(__half2*)&u0.w);
            float2 q0 = __half22float2(*(__half2*)&u1.x);
            float2 q1 = __half22float2(*(__half2*)&u1.y);
            float2 q2 = __half22float2(*(__half2*)&u1.z);
            float2 q3 = __half22float2(*(__half2*)&u1.w);
            a0x += al0 * p0.x + al1 * q0.x;  a0y += al0 * p0.y + al1 * q0.y;
            a0z += al0 * p1.x + al1 * q1.x;  a0w += al0 * p1.y + al1 * q1.y;
            a1x += al0 * p2.x + al1 * q2.x;  a1y += al0 * p2.y + al1 * q2.y;
            a1z += al0 * p3.x + al1 * q3.x;  a1w += al0 * p3.y + al1 * q3.y;
        }
        if (i < deg) {
            float al0 = (&s_sc[w][i].x)[head];
            uint4 u0 = *(const uint4*)(hsrc + (size_t)s_src[w][i] * FEAT_ + col);
            float2 p0 = __half22float2(*(__half2*)&u0.x);
            float2 p1 = __half22float2(*(__half2*)&u0.y);
            float2 p2 = __half22float2(*(__half2*)&u0.z);
            float2 p3 = __half22float2(*(__half2*)&u0.w);
            a0x += al0 * p0.x;  a0y += al0 * p0.y;
            a0z += al0 * p1.x;  a0w += al0 * p1.y;
            a1x += al0 * p2.x;  a1y += al0 * p2.y;
            a1z += al0 * p3.x;  a1w += al0 * p3.y;
        }
    } else if (deg > ECAP) {
        float m = -CUDART_INF_F;
        for (int i = l8; i < deg; i += 8) {
            int s = src[b + i];
            m = fmaxf(m, lrelu(el[s * 4 + head] + ern_h));
        }
#pragma unroll
        for (int off = 4; off > 0; off >>= 1)
            m = fmaxf(m, __shfl_xor_sync(0xffffffffu, m, off));
        float ssum = 0.f;
        for (int i = l8; i < deg; i += 8) {
            int s = src[b + i];
            ssum += __expf(lrelu(el[s * 4 + head] + ern_h) - m);
        }
#pragma unroll
        for (int off = 4; off > 0; off >>= 1)
            ssum += __shfl_xor_sync(0xffffffffu, ssum, off);
        float inv = 1.f / ssum;
        for (int i = 0; i < deg; i++) {
            int s = src[b + i];
            float a = __expf(lrelu(el[s * 4 + head] + ern_h) - m) * inv;
            uint4 u0 = *(const uint4*)(hsrc + (size_t)s * FEAT_ + col);
            float2 p0 = __half22float2(*(__half2*)&u0.x);
            float2 p1 = __half22float2(*(__half2*)&u0.y);
            float2 p2 = __half22float2(*(__half2*)&u0.z);
            float2 p3 = __half22float2(*(__half2*)&u0.w);
            a0x += a * p0.x;  a0y += a * p0.y;
            a0z += a * p1.x;  a0w += a * p1.y;
            a1x += a * p2.x;  a1y += a * p2.y;
            a1z += a * p3.x;  a1w += a * p3.y;
        }
    }

    float4 bb0 = *(const float4*)(bias + col);
    float4 bb1 = *(const float4*)(bias + col + 4);
    a0x += bb0.x; a0y += bb0.y; a0z += bb0.z; a0w += bb0.w;
    a1x += bb1.x; a1y += bb1.y; a1z += bb1.z; a1w += bb1.w;

    if (!MEAN) {
        float4* op = (float4*)(out + (size_t)n * FEAT_ + col);
        op[0] = make_float4(a0x, a0y, a0z, a0w);
        op[1] = make_float4(a1x, a1y, a1z, a1w);
    } else {
        float v[8] = {a0x, a0y, a0z, a0w, a1x, a1y, a1z, a1w};
#pragma unroll
        for (int j = 0; j < 8; j++) {
            v[j] += __shfl_xor_sync(0xffffffffu, v[j], 8);
            v[j] += __shfl_xor_sync(0xffffffffu, v[j], 16);
            v[j] *= 0.25f;
        }
        if (head == 0) {
            float4* op = (float4*)(out + (size_t)n * CDIM_ + l8 * 8);
            op[0] = make_float4(v[0], v[1], v[2], v[3]);
            op[1] = make_float4(v[4], v[5], v[6], v[7]);
        }
    }
}

// ---------------------------------------------------------------------------
// Launch
// ---------------------------------------------------------------------------
extern "C" void kernel_launch(void* const* d_in, const int* in_sizes, int n_in,
                              void* d_out, int out_size) {
    const float* x   = (const float*)d_in[0];
    const int*   src = (const int*)  d_in[1];
    const int*   dst = (const int*)  d_in[2];
    const float* W1  = (const float*)d_in[3];
    const float* al1 = (const float*)d_in[4];
    const float* ar1 = (const float*)d_in[5];
    const float* b1  = (const float*)d_in[6];
    const float* W2  = (const float*)d_in[7];
    const float* al2 = (const float*)d_in[8];
    const float* ar2 = (const float*)d_in[9];
    const float* b2  = (const float*)d_in[10];
    float* out = (float*)d_out;

    float *out1, *el, *er;
    __half *h1, *h2, *W1h, *W2h;
    cudaGetSymbolAddress((void**)&h1,   g_h1);
    cudaGetSymbolAddress((void**)&h2,   g_h2);
    cudaGetSymbolAddress((void**)&out1, g_out1);
    cudaGetSymbolAddress((void**)&el,   g_el);
    cudaGetSymbolAddress((void**)&er,   g_er);
    cudaGetSymbolAddress((void**)&W1h,  g_W1h);
    cudaGetSymbolAddress((void**)&W2h,  g_W2h);

    cudaFuncSetAttribute(gemm_f16, cudaFuncAttributeMaxDynamicSharedMemorySize, GEMM_SMEM);

    dim3 gemmGrid(MTILES, 2);
    const int edgeGrid = NNODES / 4;   // 12500

    build_rowptr<<<(NNODES + 256) / 256, 256>>>(dst);
    split_bT2<<<(2 * FEAT_ * FEAT_ + 255) / 256, 256>>>(W1, W2, W1h, W2h);

    // ---- Layer 1 ----
    gemm_f16<<<gemmGrid, 512, GEMM_SMEM>>>(x, W1h, h1, al1, ar1, el, er, NNODES);
    edge_fused<false><<<edgeGrid, 128>>>(h1, src, el, er, b1, out1);

    // ---- Layer 2 ----
    gemm_f16<<<gemmGrid, 512, GEMM_SMEM>>>(out1, W2h, h2, al2, ar2, el, er, NNODES);
    edge_fused<true><<<edgeGrid, 128>>>(h2, src, el, er, b2, out);
}